// round 7
// baseline (speedup 1.0000x reference)
#include <cuda_runtime.h>
#include <cuda_fp16.h>

#define NN 50000
#define EE 800000
#define HIDD 64
#define HC 256

// ---------------- device scratch (static, no allocation) ----------------
__device__ __align__(16) __half g_xh[NN * HC];      // per-layer features fp16
__device__ __align__(16) float g_alphap[EE * 4];    // exp(alpha) in CSR order
__device__ int g_srcp[EE];                          // src per CSR position
__device__ __align__(16) float g_asrc[NN * 4];
__device__ __align__(16) float g_adst[NN * 4];
__device__ __align__(16) float g_zbuf[NN * HIDD];   // inter-layer z
__device__ int g_src[EE];
__device__ int g_dst[EE];
__device__ int g_eid[EE];
__device__ int g_deg[NN];
__device__ int g_excl[NN];
__device__ int g_rowptr[NN + 1];
__device__ int g_wpos[NN];
__device__ int g_btot[64];
__device__ int g_boff[64];
__device__ float g_Wae[24];
__device__ int g_is32;

__device__ __forceinline__ float lrelu(float v) { return v > 0.f ? v : 0.2f * v; }

// ---------------- dtype detect: int64 vs int32 edge_index ----------------
__global__ void k_detect(const void* __restrict__ ei) {
    if (threadIdx.x == 0) g_is32 = 0;
    __syncthreads();
    const long long* p = (const long long*)ei;
    long long v = p[threadIdx.x];
    if (v < 0 || v >= NN) atomicExch(&g_is32, 1);
}

// ---------------- CSR build ----------------
__global__ void k_zero_deg() {
    int i = blockIdx.x * blockDim.x + threadIdx.x;
    if (i < NN) g_deg[i] = 0;
}

__global__ void k_convert(const void* __restrict__ ei) {
    int e = blockIdx.x * blockDim.x + threadIdx.x;
    if (e >= EE) return;
    int s, d;
    if (g_is32) {
        const int* p = (const int*)ei;
        s = p[e];
        d = p[EE + e];
    } else {
        const long long* p = (const long long*)ei;
        s = (int)p[e];
        d = (int)p[EE + e];
    }
    s = (s < 0) ? 0 : (s >= NN ? NN - 1 : s);
    d = (d < 0) ? 0 : (d >= NN ? NN - 1 : d);
    g_src[e] = s;
    g_dst[e] = d;
    atomicAdd(&g_deg[d], 1);
}

__global__ void k_scan1() {
    __shared__ int s[1024];
    int t = threadIdx.x;
    int i = blockIdx.x * 1024 + t;
    int v = (i < NN) ? g_deg[i] : 0;
    s[t] = v;
    __syncthreads();
    for (int off = 1; off < 1024; off <<= 1) {
        int tv = (t >= off) ? s[t - off] : 0;
        __syncthreads();
        s[t] += tv;
        __syncthreads();
    }
    if (i < NN) g_excl[i] = s[t] - v;
    if (t == 1023) g_btot[blockIdx.x] = s[1023];
}

__global__ void k_scan2(int nb) {
    if (threadIdx.x == 0) {
        int run = 0;
        for (int b = 0; b < nb; b++) { g_boff[b] = run; run += g_btot[b]; }
        g_rowptr[NN] = run;
    }
}

__global__ void k_scan3() {
    int i = blockIdx.x * blockDim.x + threadIdx.x;
    if (i < NN) {
        int v = g_excl[i] + g_boff[i >> 10];
        g_rowptr[i] = v;
        g_wpos[i] = v;
    }
}

__global__ void k_scatter() {
    int e = blockIdx.x * blockDim.x + threadIdx.x;
    if (e >= EE) return;
    int d = g_dst[e];
    int p = atomicAdd(&g_wpos[d], 1);
    g_eid[p] = e;
}

// ---------------- tiny weight folds ----------------
__global__ void k_wae(const float* __restrict__ att_edge,
                      const float* __restrict__ lin_edge_W) {
    int t = threadIdx.x;
    if (t >= 24) return;
    int l = t / 12;
    int r = t % 12;
    int d = r / 4;
    int h = r % 4;
    float acc = 0.f;
    for (int c = 0; c < 64; c++)
        acc += att_edge[l * 256 + h * 64 + c] * lin_edge_W[l * 768 + (h * 64 + c) * 3 + d];
    g_Wae[l * 12 + d * 4 + h] = acc;
}

// ---------------- GEMM: x = z @ W^T (fp16 out), fused a_src/a_dst ------
// (R4 static-smem scalar-FFMA version — known good.)
__global__ void k_gemm(const float* __restrict__ hin, int layer,
                       const float* __restrict__ linW,
                       const float* __restrict__ attS,
                       const float* __restrict__ attD) {
    __shared__ float Wsm[64 * 132];  // [64 k][128 cols + pad 4]
    const int half_ = blockIdx.y;
    const float* zin = (layer == 0) ? hin : g_zbuf;
    int tid = threadIdx.x;
    for (int idx = tid; idx < 128 * 64; idx += 256) {
        int k = idx & 63;
        int j = idx >> 6;
        Wsm[k * 132 + j] = linW[(half_ * 128 + j) * 64 + k];
    }
    __syncthreads();
    int lane = tid & 31;
    int gw = blockIdx.x * 8 + (tid >> 5);
    int nw = gridDim.x * 8;
    for (int n4 = gw * 4; n4 < NN; n4 += nw * 4) {
        float z0[4], z1[4];
#pragma unroll
        for (int i = 0; i < 4; i++) {
            z0[i] = zin[(n4 + i) * 64 + lane];
            z1[i] = zin[(n4 + i) * 64 + 32 + lane];
        }
        float acc[4][4];
#pragma unroll
        for (int i = 0; i < 4; i++)
#pragma unroll
            for (int j = 0; j < 4; j++) acc[i][j] = 0.f;
#pragma unroll
        for (int k = 0; k < 64; k++) {
            float zk[4];
#pragma unroll
            for (int i = 0; i < 4; i++)
                zk[i] = __shfl_sync(0xffffffffu, (k < 32) ? z0[i] : z1[i], k & 31);
#pragma unroll
            for (int j = 0; j < 4; j++) {
                float wv = Wsm[k * 132 + lane + 32 * j];
#pragma unroll
                for (int i = 0; i < 4; i++) acc[i][j] = fmaf(zk[i], wv, acc[i][j]);
            }
        }
#pragma unroll
        for (int i = 0; i < 4; i++) {
            int n = n4 + i;
#pragma unroll
            for (int j = 0; j < 4; j++)
                g_xh[n * 256 + half_ * 128 + lane + 32 * j] = __float2half(acc[i][j]);
            float ps[2], pd[2];
#pragma unroll
            for (int hl = 0; hl < 2; hl++) {
                int h = half_ * 2 + hl;
                float s0 = attS[h * 64 + lane], s1 = attS[h * 64 + 32 + lane];
                float d0 = attD[h * 64 + lane], d1 = attD[h * 64 + 32 + lane];
                ps[hl] = acc[i][2 * hl] * s0 + acc[i][2 * hl + 1] * s1;
                pd[hl] = acc[i][2 * hl] * d0 + acc[i][2 * hl + 1] * d1;
            }
#pragma unroll
            for (int hl = 0; hl < 2; hl++) {
#pragma unroll
                for (int off = 16; off > 0; off >>= 1) {
                    ps[hl] += __shfl_xor_sync(0xffffffffu, ps[hl], off);
                    pd[hl] += __shfl_xor_sync(0xffffffffu, pd[hl], off);
                }
            }
            if (lane == 0) {
                *reinterpret_cast<float2*>(g_asrc + 4 * n + half_ * 2) = make_float2(ps[0], ps[1]);
                *reinterpret_cast<float2*>(g_adst + 4 * n + half_ * 2) = make_float2(pd[0], pd[1]);
            }
        }
    }
}

// ---------------- pass A: exp(alpha) in CSR order (no atomics) ----------
__global__ void k_passA(int l, const float* __restrict__ ea) {
    int p = blockIdx.x * blockDim.x + threadIdx.x;
    if (p >= EE) return;
    int e = g_eid[p];
    int s = g_src[e], d = g_dst[e];
    float e0 = ea[3 * e], e1 = ea[3 * e + 1], e2 = ea[3 * e + 2];
    const float* W = g_Wae + l * 12;
    float4 as = *reinterpret_cast<const float4*>(g_asrc + 4 * s);
    float4 ad = *reinterpret_cast<const float4*>(g_adst + 4 * d);
    float4 al;
    al.x = __expf(lrelu(as.x + ad.x + e0 * W[0] + e1 * W[4] + e2 * W[8]));
    al.y = __expf(lrelu(as.y + ad.y + e0 * W[1] + e1 * W[5] + e2 * W[9]));
    al.z = __expf(lrelu(as.z + ad.z + e0 * W[2] + e1 * W[6] + e2 * W[10]));
    al.w = __expf(lrelu(as.w + ad.w + e0 * W[3] + e1 * W[7] + e2 * W[11]));
    *reinterpret_cast<float4*>(g_alphap + 4 * p) = al;
    g_srcp[p] = s;
}

// ---------------- aggregation: warp per dst node ------------------------
__global__ void k_agg(const float* __restrict__ bias, const float* __restrict__ gamma,
                      const float* __restrict__ beta, float* __restrict__ dout, int layer) {
    int gtid = blockIdx.x * blockDim.x + threadIdx.x;
    int n = gtid >> 5;
    if (n >= NN) return;
    int lane = gtid & 31;
    int hd = lane >> 3;
    int sub = lane & 7;
    int beg = g_rowptr[n], end = g_rowptr[n + 1];
    int deg = end - beg;

    // softmax denominator (values are already exp'd)
    float dacc = 0.f;
    for (int idx = lane; idx < deg * 4; idx += 32)
        dacc += g_alphap[beg * 4 + idx];
    dacc += __shfl_xor_sync(0xffffffffu, dacc, 4);
    dacc += __shfl_xor_sync(0xffffffffu, dacc, 8);
    dacc += __shfl_xor_sync(0xffffffffu, dacc, 16);
    float den = __shfl_sync(0xffffffffu, dacc, hd);
    float invd = 1.f / (den + 1e-16f);

    float a[8] = {0.f, 0.f, 0.f, 0.f, 0.f, 0.f, 0.f, 0.f};
    int p = beg;
    for (; p + 1 < end; p += 2) {
        int s0 = g_srcp[p], s1 = g_srcp[p + 1];
        float w0 = g_alphap[4 * p + hd];
        float w1 = g_alphap[4 * (p + 1) + hd];
        uint4 raw0 = *reinterpret_cast<const uint4*>(g_xh + s0 * 256 + lane * 8);
        uint4 raw1 = *reinterpret_cast<const uint4*>(g_xh + s1 * 256 + lane * 8);
        const __half2* h0 = reinterpret_cast<const __half2*>(&raw0);
        const __half2* h1 = reinterpret_cast<const __half2*>(&raw1);
#pragma unroll
        for (int q = 0; q < 4; q++) {
            float2 f0 = __half22float2(h0[q]);
            float2 f1 = __half22float2(h1[q]);
            a[2 * q] = fmaf(w0, f0.x, a[2 * q]);
            a[2 * q + 1] = fmaf(w0, f0.y, a[2 * q + 1]);
            a[2 * q] = fmaf(w1, f1.x, a[2 * q]);
            a[2 * q + 1] = fmaf(w1, f1.y, a[2 * q + 1]);
        }
    }
    if (p < end) {
        int s0 = g_srcp[p];
        float w0 = g_alphap[4 * p + hd];
        uint4 raw0 = *reinterpret_cast<const uint4*>(g_xh + s0 * 256 + lane * 8);
        const __half2* h0 = reinterpret_cast<const __half2*>(&raw0);
#pragma unroll
        for (int q = 0; q < 4; q++) {
            float2 f0 = __half22float2(h0[q]);
            a[2 * q] = fmaf(w0, f0.x, a[2 * q]);
            a[2 * q + 1] = fmaf(w0, f0.y, a[2 * q + 1]);
        }
    }
#pragma unroll
    for (int q = 0; q < 8; q++) {
        a[q] *= invd;  // per-head normalization before cross-head sum
        a[q] += __shfl_xor_sync(0xffffffffu, a[q], 8);
        a[q] += __shfl_xor_sync(0xffffffffu, a[q], 16);
    }
    float s1 = 0.f, s2 = 0.f;
#pragma unroll
    for (int i = 0; i < 8; i++) {
        a[i] = a[i] * 0.25f + bias[sub * 8 + i];
        s1 += a[i];
        s2 += a[i] * a[i];
    }
#pragma unroll
    for (int off = 1; off <= 4; off <<= 1) {
        s1 += __shfl_xor_sync(0xffffffffu, s1, off);
        s2 += __shfl_xor_sync(0xffffffffu, s2, off);
    }
    float mu = s1 * (1.f / 64.f);
    float var = s2 * (1.f / 64.f) - mu * mu;
    float rstd = rsqrtf(var + 1e-5f);
    float* zout = (layer == 1) ? dout : g_zbuf;
    if (lane < 8) {
        float res[8];
#pragma unroll
        for (int i = 0; i < 8; i++) {
            int c = sub * 8 + i;
            float ln = (a[i] - mu) * rstd * gamma[c] + beta[c];
            res[i] = ln / (1.f + __expf(-ln));
        }
        float4* op = reinterpret_cast<float4*>(zout + n * 64 + sub * 8);
        op[0] = make_float4(res[0], res[1], res[2], res[3]);
        op[1] = make_float4(res[4], res[5], res[6], res[7]);
    }
}

// ---------------- launch ----------------
extern "C" void kernel_launch(void* const* d_in, const int* in_sizes, int n_in,
                              void* d_out, int out_size) {
    const float* h = (const float*)d_in[1];
    const void* ei = d_in[2];
    const float* ea = (const float*)d_in[3];
    const float* linW = (const float*)d_in[4];
    const float* linEW = (const float*)d_in[5];
    const float* attS = (const float*)d_in[6];
    const float* attD = (const float*)d_in[7];
    const float* attE = (const float*)d_in[8];
    const float* bias = (const float*)d_in[9];
    const float* gamma = (const float*)d_in[10];
    const float* beta = (const float*)d_in[11];
    float* dout = (float*)d_out;

    k_detect<<<1, 1024>>>(ei);
    k_zero_deg<<<(NN + 255) / 256, 256>>>();
    k_convert<<<(EE + 255) / 256, 256>>>(ei);
    k_scan1<<<(NN + 1023) / 1024, 1024>>>();
    k_scan2<<<1, 32>>>((NN + 1023) / 1024);
    k_scan3<<<(NN + 255) / 256, 256>>>();
    k_scatter<<<(EE + 255) / 256, 256>>>();
    k_wae<<<1, 32>>>(attE, linEW);

    for (int l = 0; l < 2; l++) {
        k_gemm<<<dim3(296, 2), 256>>>(h, l, linW + l * 256 * 64, attS + l * 256, attD + l * 256);
        k_passA<<<(EE + 255) / 256, 256>>>(l, ea);
        k_agg<<<(NN * 32 + 255) / 256, 256>>>(bias + l * 64, gamma + l * 64, beta + l * 64, dout, l);
    }
}

// round 11
// speedup vs baseline: 1.6013x; 1.6013x over previous
#include <cuda_runtime.h>
#include <cuda_fp16.h>

#define NN 50000
#define EE 800000
#define HIDD 64
#define HC 256

// ---------------- device scratch (static, no allocation) ----------------
__device__ __align__(16) __half g_xh[NN * HC];      // per-layer features fp16
__device__ __align__(16) float g_alphap[EE * 4];    // exp(alpha) in CSR order
__device__ int g_srcp[EE];                          // src per CSR position
__device__ __align__(16) float g_asrc[NN * 4];
__device__ __align__(16) float g_adst[NN * 4];
__device__ __align__(16) float g_zbuf[NN * HIDD];   // inter-layer z
__device__ int g_src[EE];
__device__ int g_dst[EE];
__device__ int g_eid[EE];
__device__ int g_deg[NN];
__device__ int g_excl[NN];
__device__ int g_rowptr[NN + 1];
__device__ int g_wpos[NN];
__device__ int g_btot[64];
__device__ int g_boff[64];
__device__ float g_Wae[24];
__device__ int g_is32;

__device__ __forceinline__ float lrelu(float v) { return v > 0.f ? v : 0.2f * v; }

// ---------------- detect dtype + zero degree (fused) --------------------
__global__ void k_detect_zero(const void* __restrict__ ei) {
    int i = blockIdx.x * blockDim.x + threadIdx.x;
    if (i < NN) g_deg[i] = 0;
    if (blockIdx.x == 0 && threadIdx.x == 0) g_is32 = 0;
    // dtype probe: first 256 int64 slots (threads of block 1)
    if (blockIdx.x == 1) {
        const long long* p = (const long long*)ei;
        long long v = p[threadIdx.x];
        if (v < 0 || v >= NN) atomicExch(&g_is32, 1);
    }
}

// ---------------- CSR build ----------------
__global__ void k_convert(const void* __restrict__ ei) {
    int e = blockIdx.x * blockDim.x + threadIdx.x;
    if (e >= EE) return;
    int s, d;
    if (g_is32) {
        const int* p = (const int*)ei;
        s = p[e];
        d = p[EE + e];
    } else {
        const long long* p = (const long long*)ei;
        s = (int)p[e];
        d = (int)p[EE + e];
    }
    s = (s < 0) ? 0 : (s >= NN ? NN - 1 : s);
    d = (d < 0) ? 0 : (d >= NN ? NN - 1 : d);
    g_src[e] = s;
    g_dst[e] = d;
    atomicAdd(&g_deg[d], 1);
}

__global__ void k_scan1() {
    __shared__ int s[1024];
    int t = threadIdx.x;
    int i = blockIdx.x * 1024 + t;
    int v = (i < NN) ? g_deg[i] : 0;
    s[t] = v;
    __syncthreads();
    for (int off = 1; off < 1024; off <<= 1) {
        int tv = (t >= off) ? s[t - off] : 0;
        __syncthreads();
        s[t] += tv;
        __syncthreads();
    }
    if (i < NN) g_excl[i] = s[t] - v;
    if (t == 1023) g_btot[blockIdx.x] = s[1023];
}

// scan2 (warp 0) + Wae fold (warp 1) fused
__global__ void k_scan2_wae(int nb, const float* __restrict__ att_edge,
                            const float* __restrict__ lin_edge_W) {
    int t = threadIdx.x;
    if (t == 0) {
        int run = 0;
        for (int b = 0; b < nb; b++) { g_boff[b] = run; run += g_btot[b]; }
        g_rowptr[NN] = run;
    } else if (t >= 32 && t < 56) {
        int u = t - 32;
        int l = u / 12;
        int r = u % 12;
        int d = r / 4;
        int h = r % 4;
        float acc = 0.f;
        for (int c = 0; c < 64; c++)
            acc += att_edge[l * 256 + h * 64 + c] * lin_edge_W[l * 768 + (h * 64 + c) * 3 + d];
        g_Wae[l * 12 + d * 4 + h] = acc;
    }
}

__global__ void k_scan3() {
    int i = blockIdx.x * blockDim.x + threadIdx.x;
    if (i < NN) {
        int v = g_excl[i] + g_boff[i >> 10];
        g_rowptr[i] = v;
        g_wpos[i] = v;
    }
}

__global__ void k_scatter() {
    int e = blockIdx.x * blockDim.x + threadIdx.x;
    if (e >= EE) return;
    int d = g_dst[e];
    int p = atomicAdd(&g_wpos[d], 1);
    g_eid[p] = e;
}

// ---------------- GEMM: x = z @ W^T (fp16 out), fused a_src/a_dst ------
__global__ void k_gemm(const float* __restrict__ hin, int layer,
                       const float* __restrict__ linW,
                       const float* __restrict__ attS,
                       const float* __restrict__ attD) {
    __shared__ float Wsm[64 * 132];  // [64 k][128 cols + pad 4]
    const int half_ = blockIdx.y;
    const float* zin = (layer == 0) ? hin : g_zbuf;
    int tid = threadIdx.x;
    for (int idx = tid; idx < 128 * 64; idx += 256) {
        int k = idx & 63;
        int j = idx >> 6;
        Wsm[k * 132 + j] = linW[(half_ * 128 + j) * 64 + k];
    }
    __syncthreads();
    int lane = tid & 31;
    int gw = blockIdx.x * 8 + (tid >> 5);
    int nw = gridDim.x * 8;
    for (int n4 = gw * 4; n4 < NN; n4 += nw * 4) {
        float z0[4], z1[4];
#pragma unroll
        for (int i = 0; i < 4; i++) {
            z0[i] = zin[(n4 + i) * 64 + lane];
            z1[i] = zin[(n4 + i) * 64 + 32 + lane];
        }
        float acc[4][4];
#pragma unroll
        for (int i = 0; i < 4; i++)
#pragma unroll
            for (int j = 0; j < 4; j++) acc[i][j] = 0.f;
#pragma unroll
        for (int k = 0; k < 64; k++) {
            float zk[4];
#pragma unroll
            for (int i = 0; i < 4; i++)
                zk[i] = __shfl_sync(0xffffffffu, (k < 32) ? z0[i] : z1[i], k & 31);
#pragma unroll
            for (int j = 0; j < 4; j++) {
                float wv = Wsm[k * 132 + lane + 32 * j];
#pragma unroll
                for (int i = 0; i < 4; i++) acc[i][j] = fmaf(zk[i], wv, acc[i][j]);
            }
        }
#pragma unroll
        for (int i = 0; i < 4; i++) {
            int n = n4 + i;
#pragma unroll
            for (int j = 0; j < 4; j++)
                g_xh[n * 256 + half_ * 128 + lane + 32 * j] = __float2half(acc[i][j]);
            float ps[2], pd[2];
#pragma unroll
            for (int hl = 0; hl < 2; hl++) {
                int h = half_ * 2 + hl;
                float s0 = attS[h * 64 + lane], s1 = attS[h * 64 + 32 + lane];
                float d0 = attD[h * 64 + lane], d1 = attD[h * 64 + 32 + lane];
                ps[hl] = acc[i][2 * hl] * s0 + acc[i][2 * hl + 1] * s1;
                pd[hl] = acc[i][2 * hl] * d0 + acc[i][2 * hl + 1] * d1;
            }
#pragma unroll
            for (int hl = 0; hl < 2; hl++) {
#pragma unroll
                for (int off = 16; off > 0; off >>= 1) {
                    ps[hl] += __shfl_xor_sync(0xffffffffu, ps[hl], off);
                    pd[hl] += __shfl_xor_sync(0xffffffffu, pd[hl], off);
                }
            }
            if (lane == 0) {
                *reinterpret_cast<float2*>(g_asrc + 4 * n + half_ * 2) = make_float2(ps[0], ps[1]);
                *reinterpret_cast<float2*>(g_adst + 4 * n + half_ * 2) = make_float2(pd[0], pd[1]);
            }
        }
    }
}

// ---------------- pass A: exp(alpha) in CSR order (no atomics) ----------
__global__ void k_passA(int l, const float* __restrict__ ea) {
    int p = blockIdx.x * blockDim.x + threadIdx.x;
    if (p >= EE) return;
    int e = g_eid[p];
    int s = g_src[e], d = g_dst[e];
    float e0 = ea[3 * e], e1 = ea[3 * e + 1], e2 = ea[3 * e + 2];
    const float* W = g_Wae + l * 12;
    float4 as = *reinterpret_cast<const float4*>(g_asrc + 4 * s);
    float4 ad = *reinterpret_cast<const float4*>(g_adst + 4 * d);
    float4 al;
    al.x = __expf(lrelu(as.x + ad.x + e0 * W[0] + e1 * W[4] + e2 * W[8]));
    al.y = __expf(lrelu(as.y + ad.y + e0 * W[1] + e1 * W[5] + e2 * W[9]));
    al.z = __expf(lrelu(as.z + ad.z + e0 * W[2] + e1 * W[6] + e2 * W[10]));
    al.w = __expf(lrelu(as.w + ad.w + e0 * W[3] + e1 * W[7] + e2 * W[11]));
    *reinterpret_cast<float4*>(g_alphap + 4 * p) = al;
    g_srcp[p] = s;
}

// ---------------- aggregation: warp per dst, single fused loop ----------
__global__ void k_agg(const float* __restrict__ bias, const float* __restrict__ gamma,
                      const float* __restrict__ beta, float* __restrict__ dout, int layer) {
    int gtid = blockIdx.x * blockDim.x + threadIdx.x;
    int n = gtid >> 5;
    if (n >= NN) return;
    int lane = gtid & 31;
    int hd = lane >> 3;
    int sub = lane & 7;
    int beg = g_rowptr[n], end = g_rowptr[n + 1];

    float a[8] = {0.f, 0.f, 0.f, 0.f, 0.f, 0.f, 0.f, 0.f};
    float dacc = 0.f;  // per-lane denominator for head hd (every lane walks all edges)
    int p = beg;
    for (; p + 3 < end; p += 4) {
        int s0 = g_srcp[p], s1 = g_srcp[p + 1], s2 = g_srcp[p + 2], s3 = g_srcp[p + 3];
        float w0 = g_alphap[4 * p + hd];
        float w1 = g_alphap[4 * (p + 1) + hd];
        float w2 = g_alphap[4 * (p + 2) + hd];
        float w3 = g_alphap[4 * (p + 3) + hd];
        uint4 r0 = *reinterpret_cast<const uint4*>(g_xh + s0 * 256 + lane * 8);
        uint4 r1 = *reinterpret_cast<const uint4*>(g_xh + s1 * 256 + lane * 8);
        uint4 r2 = *reinterpret_cast<const uint4*>(g_xh + s2 * 256 + lane * 8);
        uint4 r3 = *reinterpret_cast<const uint4*>(g_xh + s3 * 256 + lane * 8);
        dacc += (w0 + w1) + (w2 + w3);
        const __half2* h0 = reinterpret_cast<const __half2*>(&r0);
        const __half2* h1 = reinterpret_cast<const __half2*>(&r1);
        const __half2* h2 = reinterpret_cast<const __half2*>(&r2);
        const __half2* h3 = reinterpret_cast<const __half2*>(&r3);
#pragma unroll
        for (int q = 0; q < 4; q++) {
            float2 f0 = __half22float2(h0[q]);
            float2 f1 = __half22float2(h1[q]);
            float2 f2 = __half22float2(h2[q]);
            float2 f3 = __half22float2(h3[q]);
            a[2 * q]     = fmaf(w0, f0.x, a[2 * q]);
            a[2 * q + 1] = fmaf(w0, f0.y, a[2 * q + 1]);
            a[2 * q]     = fmaf(w1, f1.x, a[2 * q]);
            a[2 * q + 1] = fmaf(w1, f1.y, a[2 * q + 1]);
            a[2 * q]     = fmaf(w2, f2.x, a[2 * q]);
            a[2 * q + 1] = fmaf(w2, f2.y, a[2 * q + 1]);
            a[2 * q]     = fmaf(w3, f3.x, a[2 * q]);
            a[2 * q + 1] = fmaf(w3, f3.y, a[2 * q + 1]);
        }
    }
    for (; p < end; ++p) {
        int s0 = g_srcp[p];
        float w0 = g_alphap[4 * p + hd];
        uint4 r0 = *reinterpret_cast<const uint4*>(g_xh + s0 * 256 + lane * 8);
        dacc += w0;
        const __half2* h0 = reinterpret_cast<const __half2*>(&r0);
#pragma unroll
        for (int q = 0; q < 4; q++) {
            float2 f0 = __half22float2(h0[q]);
            a[2 * q]     = fmaf(w0, f0.x, a[2 * q]);
            a[2 * q + 1] = fmaf(w0, f0.y, a[2 * q + 1]);
        }
    }
    float invd = 1.f / (dacc + 1e-16f);
#pragma unroll
    for (int q = 0; q < 8; q++) {
        a[q] *= invd;  // per-head normalization before cross-head sum
        a[q] += __shfl_xor_sync(0xffffffffu, a[q], 8);
        a[q] += __shfl_xor_sync(0xffffffffu, a[q], 16);
    }
    float s1 = 0.f, s2 = 0.f;
#pragma unroll
    for (int i = 0; i < 8; i++) {
        a[i] = a[i] * 0.25f + bias[sub * 8 + i];
        s1 += a[i];
        s2 += a[i] * a[i];
    }
#pragma unroll
    for (int off = 1; off <= 4; off <<= 1) {
        s1 += __shfl_xor_sync(0xffffffffu, s1, off);
        s2 += __shfl_xor_sync(0xffffffffu, s2, off);
    }
    float mu = s1 * (1.f / 64.f);
    float var = s2 * (1.f / 64.f) - mu * mu;
    float rstd = rsqrtf(var + 1e-5f);
    float* zout = (layer == 1) ? dout : g_zbuf;
    if (lane < 8) {
        float res[8];
#pragma unroll
        for (int i = 0; i < 8; i++) {
            int c = sub * 8 + i;
            float ln = (a[i] - mu) * rstd * gamma[c] + beta[c];
            res[i] = ln / (1.f + __expf(-ln));
        }
        float4* op = reinterpret_cast<float4*>(zout + n * 64 + sub * 8);
        op[0] = make_float4(res[0], res[1], res[2], res[3]);
        op[1] = make_float4(res[4], res[5], res[6], res[7]);
    }
}

// ---------------- launch ----------------
extern "C" void kernel_launch(void* const* d_in, const int* in_sizes, int n_in,
                              void* d_out, int out_size) {
    const float* h = (const float*)d_in[1];
    const void* ei = d_in[2];
    const float* ea = (const float*)d_in[3];
    const float* linW = (const float*)d_in[4];
    const float* linEW = (const float*)d_in[5];
    const float* attS = (const float*)d_in[6];
    const float* attD = (const float*)d_in[7];
    const float* attE = (const float*)d_in[8];
    const float* bias = (const float*)d_in[9];
    const float* gamma = (const float*)d_in[10];
    const float* beta = (const float*)d_in[11];
    float* dout = (float*)d_out;

    k_detect_zero<<<(NN + 255) / 256, 256>>>(ei);
    k_convert<<<(EE + 255) / 256, 256>>>(ei);
    k_scan1<<<(NN + 1023) / 1024, 1024>>>();
    k_scan2_wae<<<1, 64>>>((NN + 1023) / 1024, attE, linEW);
    k_scan3<<<(NN + 255) / 256, 256>>>();
    k_scatter<<<(EE + 255) / 256, 256>>>();

    for (int l = 0; l < 2; l++) {
        k_gemm<<<dim3(296, 2), 256>>>(h, l, linW + l * 256 * 64, attS + l * 256, attD + l * 256);
        k_passA<<<(EE + 255) / 256, 256>>>(l, ea);
        k_agg<<<(NN * 32 + 255) / 256, 256>>>(bias + l * 64, gamma + l * 64, beta + l * 64, dout, l);
    }
}